// round 1
// baseline (speedup 1.0000x reference)
#include <cuda_runtime.h>
#include <math.h>

#define N_NODES 100000
#define N_EDGES 400000
#define N_GRAPHS 4096
#define D0 78
#define D1 78
#define D2 156
#define D3 312
#define DH 1024
#define DOUT 128

// ---------------- scratch (device globals; no allocation allowed) ----------------
__device__ float g_A[(size_t)N_NODES * D3];      // activations / agg buffer
__device__ float g_B[(size_t)N_NODES * D3];      // xW buffer
__device__ float g_dinv[N_NODES];
__device__ float g_pool[(size_t)N_GRAPHS * D3];
__device__ float g_cnt[N_GRAPHS];
__device__ float g_g[(size_t)N_GRAPHS * D3];
__device__ float g_fused[(size_t)N_GRAPHS * D3];
__device__ float g_h[(size_t)N_GRAPHS * DH];

// ---------------- utility kernels ----------------
__global__ void zero_kernel(float* __restrict__ p, size_t n) {
    size_t i = (size_t)blockIdx.x * blockDim.x + threadIdx.x;
    if (i < n) p[i] = 0.0f;
}

__global__ void deg_init_kernel(float* __restrict__ deg) {
    int i = blockIdx.x * blockDim.x + threadIdx.x;
    if (i < N_NODES) deg[i] = 1.0f;   // self-loop
}

__global__ void deg_count_kernel(const int* __restrict__ dst, float* __restrict__ deg) {
    int e = blockIdx.x * blockDim.x + threadIdx.x;
    if (e < N_EDGES) atomicAdd(&deg[dst[e]], 1.0f);
}

__global__ void deg_rsqrt_kernel(float* __restrict__ dinv) {
    int i = blockIdx.x * blockDim.x + threadIdx.x;
    if (i < N_NODES) dinv[i] = rsqrtf(dinv[i]);
}

// ---------------- tiled fp32 GEMM: C[M,N] = A[M,K] @ B[K,N] (+bias)(+relu) ----------------
// 64x64 tile, BK=16, 256 threads, 4x4 microtile per thread.
#define GBM 64
#define GBN 64
#define GBK 16
__global__ __launch_bounds__(256) void gemm_kernel(
    const float* __restrict__ A, const float* __restrict__ B,
    const float* __restrict__ bias, float* __restrict__ C,
    int M, int K, int N, int mode /*0=none,1=bias,2=bias+relu*/) {
    __shared__ float As[GBK][GBM];
    __shared__ float Bs[GBK][GBN + 4];
    int tid = threadIdx.x;
    int tx = tid & 15;        // N dir
    int ty = tid >> 4;        // M dir
    int row0 = blockIdx.y * GBM;
    int col0 = blockIdx.x * GBN;

    float acc[4][4] = {};
    for (int k0 = 0; k0 < K; k0 += GBK) {
        // load A tile (64x16 = 1024 elems)
        #pragma unroll
        for (int t = 0; t < 4; t++) {
            int idx = tid + t * 256;
            int m = idx >> 4;          // idx / GBK
            int kk = idx & 15;         // idx % GBK
            int gm = row0 + m, gk = k0 + kk;
            As[kk][m] = (gm < M && gk < K) ? A[(size_t)gm * K + gk] : 0.0f;
        }
        // load B tile (16x64)
        #pragma unroll
        for (int t = 0; t < 4; t++) {
            int idx = tid + t * 256;
            int kk = idx >> 6;         // idx / GBN
            int n  = idx & 63;         // idx % GBN
            int gk = k0 + kk, gn = col0 + n;
            Bs[kk][n] = (gk < K && gn < N) ? B[(size_t)gk * N + gn] : 0.0f;
        }
        __syncthreads();
        #pragma unroll
        for (int kk = 0; kk < GBK; kk++) {
            float a[4], b[4];
            #pragma unroll
            for (int i = 0; i < 4; i++) a[i] = As[kk][ty * 4 + i];
            #pragma unroll
            for (int j = 0; j < 4; j++) b[j] = Bs[kk][tx * 4 + j];
            #pragma unroll
            for (int i = 0; i < 4; i++)
                #pragma unroll
                for (int j = 0; j < 4; j++)
                    acc[i][j] = fmaf(a[i], b[j], acc[i][j]);
        }
        __syncthreads();
    }
    #pragma unroll
    for (int i = 0; i < 4; i++) {
        int gm = row0 + ty * 4 + i;
        if (gm >= M) continue;
        #pragma unroll
        for (int j = 0; j < 4; j++) {
            int gn = col0 + tx * 4 + j;
            if (gn >= N) continue;
            float v = acc[i][j];
            if (mode >= 1) v += bias[gn];
            if (mode == 2) v = fmaxf(v, 0.0f);
            C[(size_t)gm * N + gn] = v;
        }
    }
}

// ---------------- edge scatter: A[dst] += B[src] * dinv[src]*dinv[dst] ----------------
// one warp per edge, lanes stride features
__global__ __launch_bounds__(256) void edge_scatter_kernel(
    const float* __restrict__ B, float* __restrict__ A,
    const int* __restrict__ src, const int* __restrict__ dst,
    const float* __restrict__ dinv, int Dout) {
    int warp = (blockIdx.x * blockDim.x + threadIdx.x) >> 5;
    int lane = threadIdx.x & 31;
    if (warp >= N_EDGES) return;
    int s = src[warp];
    int d = dst[warp];
    float norm = dinv[s] * dinv[d];
    const float* __restrict__ brow = B + (size_t)s * Dout;
    float* __restrict__ arow = A + (size_t)d * Dout;
    for (int f = lane; f < Dout; f += 32)
        atomicAdd(&arow[f], brow[f] * norm);
}

// ---------------- finalize: A = relu(A + B*dinv^2 + bias) ----------------
__global__ void finalize_kernel(float* __restrict__ A, const float* __restrict__ B,
                                const float* __restrict__ bias,
                                const float* __restrict__ dinv, int Dout) {
    size_t idx = (size_t)blockIdx.x * blockDim.x + threadIdx.x;
    size_t total = (size_t)N_NODES * Dout;
    if (idx >= total) return;
    int i = (int)(idx / Dout);
    int f = (int)(idx % Dout);
    float di = dinv[i];
    float v = A[idx] + B[idx] * di * di + bias[f];
    A[idx] = fmaxf(v, 0.0f);
}

// ---------------- mean pool over graphs ----------------
__global__ __launch_bounds__(256) void pool_kernel(
    const float* __restrict__ X, const int* __restrict__ batch,
    float* __restrict__ pooled, float* __restrict__ cnt) {
    int warp = (blockIdx.x * blockDim.x + threadIdx.x) >> 5;
    int lane = threadIdx.x & 31;
    if (warp >= N_NODES) return;
    int g = batch[warp];
    if (lane == 0) atomicAdd(&cnt[g], 1.0f);
    const float* __restrict__ xrow = X + (size_t)warp * D3;
    float* __restrict__ prow = pooled + (size_t)g * D3;
    for (int f = lane; f < D3; f += 32)
        atomicAdd(&prow[f], xrow[f]);
}

__global__ void pool_div_kernel(float* __restrict__ pooled, const float* __restrict__ cnt) {
    int idx = blockIdx.x * blockDim.x + threadIdx.x;
    if (idx >= N_GRAPHS * D3) return;
    int g = idx / D3;
    pooled[idx] /= fmaxf(cnt[g], 1.0f);
}

// ---------------- gate + fuse: one warp per graph ----------------
__global__ __launch_bounds__(256) void gate_fuse_kernel(
    const float* __restrict__ pooled, const float* __restrict__ gvec,
    const float* __restrict__ Wgate, const float* __restrict__ bgate,
    float* __restrict__ fused) {
    int warp = (blockIdx.x * blockDim.x + threadIdx.x) >> 5;
    int lane = threadIdx.x & 31;
    if (warp >= N_GRAPHS) return;
    const float* __restrict__ prow = pooled + (size_t)warp * D3;
    const float* __restrict__ grow = gvec + (size_t)warp * D3;
    float t = 0.0f;
    for (int f = lane; f < D3; f += 32)
        t += prow[f] * Wgate[f] + grow[f] * Wgate[D3 + f];
    #pragma unroll
    for (int off = 16; off > 0; off >>= 1)
        t += __shfl_xor_sync(0xFFFFFFFF, t, off);
    t += bgate[0];
    float gate = 1.0f / (1.0f + expf(-t));
    gate = __shfl_sync(0xFFFFFFFF, gate, 0);
    float* __restrict__ frow = fused + (size_t)warp * D3;
    for (int f = lane; f < D3; f += 32)
        frow[f] = gate * grow[f] + (1.0f - gate) * prow[f];
}

// ---------------- host ----------------
static inline int cdiv(int a, int b) { return (a + b - 1) / b; }

extern "C" void kernel_launch(void* const* d_in, const int* in_sizes, int n_in,
                              void* d_out, int out_size) {
    const float* mol_x  = (const float*)d_in[0];
    const int*   edges  = (const int*)d_in[1];
    const int*   batch  = (const int*)d_in[2];
    const float* gemb   = (const float*)d_in[3];
    const float* W1     = (const float*)d_in[4];
    const float* b1     = (const float*)d_in[5];
    const float* W2     = (const float*)d_in[6];
    const float* b2     = (const float*)d_in[7];
    const float* W3     = (const float*)d_in[8];
    const float* b3     = (const float*)d_in[9];
    const float* Wfc1   = (const float*)d_in[10];
    const float* bfc1   = (const float*)d_in[11];
    const float* Wfc2   = (const float*)d_in[12];
    const float* bfc2   = (const float*)d_in[13];
    const float* Wproj  = (const float*)d_in[14];
    const float* bproj  = (const float*)d_in[15];
    const float* Wgate  = (const float*)d_in[16];
    const float* bgate  = (const float*)d_in[17];
    float* out = (float*)d_out;

    const int* src = edges;
    const int* dst = edges + N_EDGES;

    float *pA, *pB, *pdinv, *ppool, *pcnt, *pg, *pfused, *ph;
    cudaGetSymbolAddress((void**)&pA, g_A);
    cudaGetSymbolAddress((void**)&pB, g_B);
    cudaGetSymbolAddress((void**)&pdinv, g_dinv);
    cudaGetSymbolAddress((void**)&ppool, g_pool);
    cudaGetSymbolAddress((void**)&pcnt, g_cnt);
    cudaGetSymbolAddress((void**)&pg, g_g);
    cudaGetSymbolAddress((void**)&pfused, g_fused);
    cudaGetSymbolAddress((void**)&ph, g_h);

    // ---- degree + dinv ----
    deg_init_kernel<<<cdiv(N_NODES, 256), 256>>>(pdinv);
    deg_count_kernel<<<cdiv(N_EDGES, 256), 256>>>(dst, pdinv);
    deg_rsqrt_kernel<<<cdiv(N_NODES, 256), 256>>>(pdinv);

    // ---- GCN layer helper (inline) ----
    // layer(X, Din, Dout, W, b): B = X@W ; A = 0 ; scatter ; A = relu(A + B*dinv^2 + b)
    {
        // Layer 1: mol_x [N,78] -> A [N,78]
        dim3 grid1(cdiv(D1, GBN), cdiv(N_NODES, GBM));
        gemm_kernel<<<grid1, 256>>>(mol_x, W1, nullptr, pB, N_NODES, D0, D1, 0);
        size_t n1 = (size_t)N_NODES * D1;
        zero_kernel<<<(unsigned)((n1 + 255) / 256), 256>>>(pA, n1);
        edge_scatter_kernel<<<cdiv(N_EDGES * 32, 256), 256>>>(pB, pA, src, dst, pdinv, D1);
        finalize_kernel<<<(unsigned)((n1 + 255) / 256), 256>>>(pA, pB, b1, pdinv, D1);
    }
    {
        // Layer 2: A [N,78] -> A [N,156]
        dim3 grid2(cdiv(D2, GBN), cdiv(N_NODES, GBM));
        gemm_kernel<<<grid2, 256>>>(pA, W2, nullptr, pB, N_NODES, D1, D2, 0);
        size_t n2 = (size_t)N_NODES * D2;
        zero_kernel<<<(unsigned)((n2 + 255) / 256), 256>>>(pA, n2);
        edge_scatter_kernel<<<cdiv(N_EDGES * 32, 256), 256>>>(pB, pA, src, dst, pdinv, D2);
        finalize_kernel<<<(unsigned)((n2 + 255) / 256), 256>>>(pA, pB, b2, pdinv, D2);
    }
    {
        // Layer 3: A [N,156] -> A [N,312]
        dim3 grid3(cdiv(D3, GBN), cdiv(N_NODES, GBM));
        gemm_kernel<<<grid3, 256>>>(pA, W3, nullptr, pB, N_NODES, D2, D3, 0);
        size_t n3 = (size_t)N_NODES * D3;
        zero_kernel<<<(unsigned)((n3 + 255) / 256), 256>>>(pA, n3);
        edge_scatter_kernel<<<cdiv(N_EDGES * 32, 256), 256>>>(pB, pA, src, dst, pdinv, D3);
        finalize_kernel<<<(unsigned)((n3 + 255) / 256), 256>>>(pA, pB, b3, pdinv, D3);
    }

    // ---- mean pool ----
    {
        size_t np = (size_t)N_GRAPHS * D3;
        zero_kernel<<<(unsigned)((np + 255) / 256), 256>>>(ppool, np);
        zero_kernel<<<cdiv(N_GRAPHS, 256), 256>>>(pcnt, (size_t)N_GRAPHS);
        pool_kernel<<<cdiv(N_NODES * 32, 256), 256>>>(pA, batch, ppool, pcnt);
        pool_div_kernel<<<cdiv(N_GRAPHS * D3, 256), 256>>>(ppool, pcnt);
    }

    // ---- g = global_emb @ Wproj + bproj  [4096,128]@[128,312] ----
    {
        dim3 gridp(cdiv(D3, GBN), cdiv(N_GRAPHS, GBM));
        gemm_kernel<<<gridp, 256>>>(gemb, Wproj, bproj, pg, N_GRAPHS, 128, D3, 1);
    }

    // ---- gate + fuse ----
    gate_fuse_kernel<<<cdiv(N_GRAPHS * 32, 256), 256>>>(ppool, pg, Wgate, bgate, pfused);

    // ---- fc1: relu(fused @ Wfc1 + bfc1)  [4096,312]@[312,1024] ----
    {
        dim3 gridf1(cdiv(DH, GBN), cdiv(N_GRAPHS, GBM));
        gemm_kernel<<<gridf1, 256>>>(pfused, Wfc1, bfc1, ph, N_GRAPHS, D3, DH, 2);
    }

    // ---- fc2: h @ Wfc2 + bfc2  [4096,1024]@[1024,128] -> out ----
    {
        dim3 gridf2(cdiv(DOUT, GBN), cdiv(N_GRAPHS, GBM));
        gemm_kernel<<<gridf2, 256>>>(ph, Wfc2, bfc2, out, N_GRAPHS, DH, DOUT, 1);
    }
}